// round 11
// baseline (speedup 1.0000x reference)
#include <cuda_runtime.h>
#include <cuda_fp16.h>
#include <cstdint>

// GRU (SEQ=1, h0=0 => w_hh unused) via warp-level HMMA m16n8k16 fragment
// chaining. Round 11: 2 M-tiles per warp with tile loop INSIDE each
// (layer, unit-group) so LDSM/bias/address overhead halves per row, while
// f16-accumulator gate MMAs keep regs <=84 -> 3 CTAs/SM (24 warps).
// Layers ping-pong A buffers (no copy MOVs). FC reuses Bf across tiles.

#define TPB     256
#define LAYERS  5
#define WSTRIDE 40    // halves per W row (80 B): conflict-free LDSM
#define NT      2     // M-tiles (16 rows) in flight per warp

struct __align__(16) Smem {
    __half  W[LAYERS * 96 * WSTRIDE];  // rows 0-63 (r,z) pre-scaled by 0.5
    __half  FCW[32 * WSTRIDE];
    __half2 BG2[LAYERS * 48];          // r fused*0.5 | z fused*0.5 | n b_ih
    __half2 BNH2[LAYERS * 16];         // n-gate b_hh pairs
    float   FCB[32];
};

__device__ __forceinline__ uint32_t pack_h2(float lo, float hi) {
    uint32_t r;
    asm("cvt.rn.f16x2.f32 %0, %1, %2;" : "=r"(r) : "f"(hi), "f"(lo));
    return r;
}
__device__ __forceinline__ uint32_t tanh2(uint32_t x) {
    uint32_t y; asm("tanh.approx.f16x2 %0, %1;" : "=r"(y) : "r"(x)); return y;
}
__device__ __forceinline__ uint32_t hfma2(uint32_t a, uint32_t b, uint32_t c) {
    uint32_t d; asm("fma.rn.f16x2 %0, %1, %2, %3;" : "=r"(d) : "r"(a), "r"(b), "r"(c));
    return d;
}
__device__ __forceinline__ uint32_t hmul2(uint32_t a, uint32_t b) {
    uint32_t d; asm("mul.rn.f16x2 %0, %1, %2;" : "=r"(d) : "r"(a), "r"(b));
    return d;
}
__device__ __forceinline__ void mma_h_bias(uint32_t* d, const uint32_t* a,
                                           const uint32_t* b, uint32_t c2) {
    asm volatile(
        "mma.sync.aligned.m16n8k16.row.col.f16.f16.f16.f16 "
        "{%0,%1}, {%2,%3,%4,%5}, {%6,%7}, {%8,%8};"
        : "=r"(d[0]), "=r"(d[1])
        : "r"(a[0]), "r"(a[1]), "r"(a[2]), "r"(a[3]), "r"(b[0]), "r"(b[1]), "r"(c2));
}
__device__ __forceinline__ void mma_h_acc(uint32_t* d, const uint32_t* a,
                                          const uint32_t* b) {
    asm volatile(
        "mma.sync.aligned.m16n8k16.row.col.f16.f16.f16.f16 "
        "{%0,%1}, {%2,%3,%4,%5}, {%6,%7}, {%0,%1};"
        : "+r"(d[0]), "+r"(d[1])
        : "r"(a[0]), "r"(a[1]), "r"(a[2]), "r"(a[3]), "r"(b[0]), "r"(b[1]));
}
__device__ __forceinline__ void mma_f_bias(float* d, const uint32_t* a, const uint32_t* b,
                                           float cx, float cy) {
    asm volatile(
        "mma.sync.aligned.m16n8k16.row.col.f32.f16.f16.f32 "
        "{%0,%1,%2,%3}, {%4,%5,%6,%7}, {%8,%9}, {%10,%11,%10,%11};"
        : "=f"(d[0]), "=f"(d[1]), "=f"(d[2]), "=f"(d[3])
        : "r"(a[0]), "r"(a[1]), "r"(a[2]), "r"(a[3]), "r"(b[0]), "r"(b[1]),
          "f"(cx), "f"(cy));
}
__device__ __forceinline__ void mma_f_acc(float* d, const uint32_t* a, const uint32_t* b) {
    asm volatile(
        "mma.sync.aligned.m16n8k16.row.col.f32.f16.f16.f32 "
        "{%0,%1,%2,%3}, {%4,%5,%6,%7}, {%8,%9}, {%0,%1,%2,%3};"
        : "+f"(d[0]), "+f"(d[1]), "+f"(d[2]), "+f"(d[3])
        : "r"(a[0]), "r"(a[1]), "r"(a[2]), "r"(a[3]), "r"(b[0]), "r"(b[1]));
}
__device__ __forceinline__ void ldsm_x4(uint32_t* r, uint32_t saddr) {
    asm volatile("ldmatrix.sync.aligned.m8n8.x4.shared.b16 {%0,%1,%2,%3}, [%4];"
        : "=r"(r[0]), "=r"(r[1]), "=r"(r[2]), "=r"(r[3]) : "r"(saddr));
}

// One GRU layer for NT tiles: Ain -> Aout (distinct buffers, no copies).
__device__ __forceinline__ void layer_step(
    const Smem& S, int l, int cp, uint32_t wbase,
    const uint32_t Ain[NT][2][4], uint32_t Aout[NT][2][4])
{
    const uint32_t H05  = 0x38003800u;   // half2(+0.5)
    const uint32_t HN05 = 0xB800B800u;   // half2(-0.5)
#pragma unroll
    for (int j = 0; j < 4; j++) {
        uint32_t Br[4], Bz[4], Bn[4];
        const uint32_t la = wbase + (uint32_t)((l * 96 + j * 8) * (WSTRIDE * 2));
        ldsm_x4(Br, la);
        ldsm_x4(Bz, la + 32 * (WSTRIDE * 2));
        ldsm_x4(Bn, la + 64 * (WSTRIDE * 2));

        const uint32_t br2 = *(const uint32_t*)&S.BG2[l * 48      + j * 4 + cp];
        const uint32_t bz2 = *(const uint32_t*)&S.BG2[l * 48 + 16 + j * 4 + cp];
        const uint32_t bi2 = *(const uint32_t*)&S.BG2[l * 48 + 32 + j * 4 + cp];
        const uint32_t bh2 = *(const uint32_t*)&S.BNH2[l * 16 + j * 4 + cp];

#pragma unroll
        for (int t = 0; t < NT; t++) {
            uint32_t Dr2[2], Dz2[2], Dn2[2];
            mma_h_bias(Dr2, Ain[t][0], Br + 0, br2); mma_h_acc(Dr2, Ain[t][1], Br + 2);
            mma_h_bias(Dz2, Ain[t][0], Bz + 0, bz2); mma_h_acc(Dz2, Ain[t][1], Bz + 2);
            mma_h_bias(Dn2, Ain[t][0], Bn + 0, bi2); mma_h_acc(Dn2, Ain[t][1], Bn + 2);
#pragma unroll
            for (int p = 0; p < 2; p++) {
                uint32_t rr2 = hfma2(tanh2(Dr2[p]), H05, H05);    // sigmoid
                uint32_t zc2 = hfma2(tanh2(Dz2[p]), HN05, H05);   // 1 - z
                uint32_t n2  = tanh2(hfma2(rr2, bh2, Dn2[p]));
                Aout[t][j >> 1][(j & 1) * 2 + p] = hmul2(zc2, n2); // (1-z)*n
            }
        }
    }
}

__global__ void __launch_bounds__(TPB, 3)
gru_hmma_kernel(const float* __restrict__ x,
                const float* __restrict__ w_ih,
                const float* __restrict__ b_ih,
                const float* __restrict__ b_hh,
                const float* __restrict__ fc_w,
                const float* __restrict__ fc_b,
                float* __restrict__ out)
{
    __shared__ Smem S;
    const int tid = threadIdx.x;

    // ---- stage weights (r/z rows scaled 0.5) + packed biases ----
    for (int i = tid; i < LAYERS * 96 * 32; i += TPB) {
        int l = i / 3072, row = (i % 3072) >> 5, k = i & 31;
        float scale = (row < 64) ? 0.5f : 1.0f;
        S.W[(l * 96 + row) * WSTRIDE + k] = __float2half(w_ih[i] * scale);
    }
    for (int i = tid; i < 32 * 32; i += TPB)
        S.FCW[(i >> 5) * WSTRIDE + (i & 31)] = __float2half(fc_w[i]);
    for (int i = tid; i < LAYERS * 48; i += TPB) {
        int l = i / 48, p = i % 48;
        float v0, v1;
        if (p < 16) {
            int u = l * 96 + 2 * p;
            v0 = 0.5f * (b_ih[u] + b_hh[u]);
            v1 = 0.5f * (b_ih[u + 1] + b_hh[u + 1]);
        } else if (p < 32) {
            int u = l * 96 + 32 + 2 * (p - 16);
            v0 = 0.5f * (b_ih[u] + b_hh[u]);
            v1 = 0.5f * (b_ih[u + 1] + b_hh[u + 1]);
        } else {
            int u = l * 96 + 64 + 2 * (p - 32);
            v0 = b_ih[u];
            v1 = b_ih[u + 1];
        }
        S.BG2[i] = __floats2half2_rn(v0, v1);
    }
    for (int i = tid; i < LAYERS * 16; i += TPB) {
        int l = i / 16, p = i % 16;
        S.BNH2[i] = __floats2half2_rn(b_hh[l * 96 + 64 + 2 * p],
                                      b_hh[l * 96 + 64 + 2 * p + 1]);
    }
    for (int i = tid; i < 32; i += TPB) S.FCB[i] = fc_b[i];
    __syncthreads();

    const int warp = tid >> 5, lane = tid & 31;
    const int qrow = lane >> 2;
    const int c    = (lane & 3) * 2;
    const int cp   = lane & 3;

    const uint32_t lm_off = (uint32_t)((lane & 7) * (WSTRIDE * 2)
                                       + ((lane >> 4) & 1) * 32
                                       + ((lane >> 3) & 1) * 16);
    const uint32_t wbase = (uint32_t)__cvta_generic_to_shared(S.W)   + lm_off;
    const uint32_t fbase = (uint32_t)__cvta_generic_to_shared(S.FCW) + lm_off;

    // warp covers 32 rows = 2 tiles of 16
    const size_t r0 = (size_t)blockIdx.x * (32 * (TPB / 32)) + warp * 32 + qrow;

    // ---- A fragments for NT tiles, layer 1, from gmem (fp32 -> f16x2) ----
    uint32_t A0[NT][2][4], A1[NT][2][4];
#pragma unroll
    for (int t = 0; t < NT; t++) {
        const size_t rt = r0 + t * 16;
#pragma unroll
        for (int q = 0; q < 2; q++) {
            const float* p0 = x + rt * 32 + q * 16 + c;
            const float* p1 = x + (rt + 8) * 32 + q * 16 + c;
            float2 v00 = *(const float2*)p0;
            float2 v10 = *(const float2*)p1;
            float2 v01 = *(const float2*)(p0 + 8);
            float2 v11 = *(const float2*)(p1 + 8);
            A0[t][q][0] = pack_h2(v00.x, v00.y);
            A0[t][q][1] = pack_h2(v10.x, v10.y);
            A0[t][q][2] = pack_h2(v01.x, v01.y);
            A0[t][q][3] = pack_h2(v11.x, v11.y);
        }
    }

    // ---- 5 GRU layers, ping-pong buffers ----
    layer_step(S, 0, cp, wbase, A0, A1);
    layer_step(S, 1, cp, wbase, A1, A0);
    layer_step(S, 2, cp, wbase, A0, A1);
    layer_step(S, 3, cp, wbase, A1, A0);
    layer_step(S, 4, cp, wbase, A0, A1);   // final hidden in A1

    // ---- FC: out = H @ fc_w^T + fc_b (f32 accum), Bf reused across tiles ----
#pragma unroll
    for (int jt = 0; jt < 4; jt++) {
        uint32_t Bf[4];
        ldsm_x4(Bf, fbase + (uint32_t)(jt * 8 * (WSTRIDE * 2)));
        const float2 fb = *(const float2*)&S.FCB[jt * 8 + c];
#pragma unroll
        for (int t = 0; t < NT; t++) {
            float D[4];
            mma_f_bias(D, A1[t][0], Bf + 0, fb.x, fb.y);
            mma_f_acc(D, A1[t][1], Bf + 2);
            const size_t rt = r0 + t * 16;
            *(float2*)&out[rt * 32       + jt * 8 + c] = make_float2(D[0], D[1]);
            *(float2*)&out[(rt + 8) * 32 + jt * 8 + c] = make_float2(D[2], D[3]);
        }
    }
}

extern "C" void kernel_launch(void* const* d_in, const int* in_sizes, int n_in,
                              void* d_out, int out_size)
{
    const float* x    = (const float*)d_in[0];
    const float* w_ih = (const float*)d_in[1];
    // d_in[2] = w_hh : unused (SEQ=1, h0=0)
    const float* b_ih = (const float*)d_in[3];
    const float* b_hh = (const float*)d_in[4];
    const float* fc_w = (const float*)d_in[5];
    const float* fc_b = (const float*)d_in[6];
    float* out = (float*)d_out;

    const int batch = in_sizes[0] / 32;          // 1048576
    const int grid  = batch / (32 * (TPB / 32)); // 4096

    gru_hmma_kernel<<<grid, TPB>>>(x, w_ih, b_ih, b_hh, fc_w, fc_b, out);
}

// round 12
// speedup vs baseline: 1.1458x; 1.1458x over previous
#include <cuda_runtime.h>
#include <cuda_fp16.h>
#include <cstdint>

// GRU (SEQ=1, h0=0 => w_hh unused) via warp-level HMMA m16n8k16 fragment
// chaining. Round 12: prep kernel pre-builds fp16 weights (r/z rows scaled
// 0.5, WSTRIDE-padded) + packed fused biases in a __device__ global; the
// main kernel stages by pure uint4 copy (~66 warp-instrs vs ~360), NTILES=4.
// Body: R7 structure (1 tile/warp in flight) + R9 f16-accumulator epilogue.

#define TPB     256
#define LAYERS  5
#define WSTRIDE 40    // halves per W row (80 B): conflict-free LDSM
#define NTILES  4     // 128-row tile-halves per CTA

struct __align__(16) Prep {
    __half  W[LAYERS * 96 * WSTRIDE];  // 38400 B  (r/z rows pre-scaled by 0.5)
    __half  FCW[32 * WSTRIDE];         //  2560 B
    __half2 BG2[LAYERS * 48];          //   960 B  r*0.5 | z*0.5 | n b_ih (pairs)
    __half2 BNH2[LAYERS * 16];         //   320 B  n-gate b_hh pairs
    float   FCB[32];                   //   128 B
};                                     // 42368 B = 2648 uint4
#define PREP_U4 (sizeof(Prep) / 16)

__device__ Prep g_prep;

// ---------------- prep kernel: runs once per launch, tiny ----------------
__global__ void gru_prep_kernel(const float* __restrict__ w_ih,
                                const float* __restrict__ b_ih,
                                const float* __restrict__ b_hh,
                                const float* __restrict__ fc_w,
                                const float* __restrict__ fc_b)
{
    const int tid = blockIdx.x * blockDim.x + threadIdx.x;
    const int nth = gridDim.x * blockDim.x;

    for (int i = tid; i < LAYERS * 96 * 32; i += nth) {
        int l = i / 3072, row = (i % 3072) >> 5, k = i & 31;
        float scale = (row < 64) ? 0.5f : 1.0f;
        g_prep.W[(l * 96 + row) * WSTRIDE + k] = __float2half(w_ih[i] * scale);
    }
    for (int i = tid; i < 32 * 32; i += nth)
        g_prep.FCW[(i >> 5) * WSTRIDE + (i & 31)] = __float2half(fc_w[i]);
    for (int i = tid; i < LAYERS * 48; i += nth) {
        int l = i / 48, p = i % 48;
        float v0, v1;
        if (p < 16) {            // r gate (rows 0..31), fused, *0.5
            int u = l * 96 + 2 * p;
            v0 = 0.5f * (b_ih[u] + b_hh[u]);
            v1 = 0.5f * (b_ih[u + 1] + b_hh[u + 1]);
        } else if (p < 32) {     // z gate (rows 32..63), fused, *0.5
            int u = l * 96 + 32 + 2 * (p - 16);
            v0 = 0.5f * (b_ih[u] + b_hh[u]);
            v1 = 0.5f * (b_ih[u + 1] + b_hh[u + 1]);
        } else {                 // n gate b_ih (rows 64..95)
            int u = l * 96 + 64 + 2 * (p - 32);
            v0 = b_ih[u];
            v1 = b_ih[u + 1];
        }
        g_prep.BG2[i] = __floats2half2_rn(v0, v1);
    }
    for (int i = tid; i < LAYERS * 16; i += nth) {
        int l = i / 16, p = i % 16;
        g_prep.BNH2[i] = __floats2half2_rn(b_hh[l * 96 + 64 + 2 * p],
                                           b_hh[l * 96 + 64 + 2 * p + 1]);
    }
    for (int i = tid; i < 32; i += nth) g_prep.FCB[i] = fc_b[i];
}

// ---------------- main kernel ----------------
__device__ __forceinline__ uint32_t pack_h2(float lo, float hi) {
    uint32_t r;
    asm("cvt.rn.f16x2.f32 %0, %1, %2;" : "=r"(r) : "f"(hi), "f"(lo));
    return r;
}
__device__ __forceinline__ uint32_t tanh2(uint32_t x) {
    uint32_t y; asm("tanh.approx.f16x2 %0, %1;" : "=r"(y) : "r"(x)); return y;
}
__device__ __forceinline__ uint32_t hfma2(uint32_t a, uint32_t b, uint32_t c) {
    uint32_t d; asm("fma.rn.f16x2 %0, %1, %2, %3;" : "=r"(d) : "r"(a), "r"(b), "r"(c));
    return d;
}
__device__ __forceinline__ uint32_t hmul2(uint32_t a, uint32_t b) {
    uint32_t d; asm("mul.rn.f16x2 %0, %1, %2;" : "=r"(d) : "r"(a), "r"(b));
    return d;
}
__device__ __forceinline__ void mma_h_bias(uint32_t* d, const uint32_t* a,
                                           const uint32_t* b, uint32_t c2) {
    asm volatile(
        "mma.sync.aligned.m16n8k16.row.col.f16.f16.f16.f16 "
        "{%0,%1}, {%2,%3,%4,%5}, {%6,%7}, {%8,%8};"
        : "=r"(d[0]), "=r"(d[1])
        : "r"(a[0]), "r"(a[1]), "r"(a[2]), "r"(a[3]), "r"(b[0]), "r"(b[1]), "r"(c2));
}
__device__ __forceinline__ void mma_h_acc(uint32_t* d, const uint32_t* a,
                                          const uint32_t* b) {
    asm volatile(
        "mma.sync.aligned.m16n8k16.row.col.f16.f16.f16.f16 "
        "{%0,%1}, {%2,%3,%4,%5}, {%6,%7}, {%0,%1};"
        : "+r"(d[0]), "+r"(d[1])
        : "r"(a[0]), "r"(a[1]), "r"(a[2]), "r"(a[3]), "r"(b[0]), "r"(b[1]));
}
__device__ __forceinline__ void mma_f_bias(float* d, const uint32_t* a, const uint32_t* b,
                                           float cx, float cy) {
    asm volatile(
        "mma.sync.aligned.m16n8k16.row.col.f32.f16.f16.f32 "
        "{%0,%1,%2,%3}, {%4,%5,%6,%7}, {%8,%9}, {%10,%11,%10,%11};"
        : "=f"(d[0]), "=f"(d[1]), "=f"(d[2]), "=f"(d[3])
        : "r"(a[0]), "r"(a[1]), "r"(a[2]), "r"(a[3]), "r"(b[0]), "r"(b[1]),
          "f"(cx), "f"(cy));
}
__device__ __forceinline__ void mma_f_acc(float* d, const uint32_t* a, const uint32_t* b) {
    asm volatile(
        "mma.sync.aligned.m16n8k16.row.col.f32.f16.f16.f32 "
        "{%0,%1,%2,%3}, {%4,%5,%6,%7}, {%8,%9}, {%0,%1,%2,%3};"
        : "+f"(d[0]), "+f"(d[1]), "+f"(d[2]), "+f"(d[3])
        : "r"(a[0]), "r"(a[1]), "r"(a[2]), "r"(a[3]), "r"(b[0]), "r"(b[1]));
}
__device__ __forceinline__ void ldsm_x4(uint32_t* r, uint32_t saddr) {
    asm volatile("ldmatrix.sync.aligned.m8n8.x4.shared.b16 {%0,%1,%2,%3}, [%4];"
        : "=r"(r[0]), "=r"(r[1]), "=r"(r[2]), "=r"(r[3]) : "r"(saddr));
}

__global__ void __launch_bounds__(TPB, 3)
gru_hmma_kernel(const float* __restrict__ x, float* __restrict__ out)
{
    __shared__ Prep S;
    const int tid = threadIdx.x;

    // ---- stage prepped package: pure vector copy (~11 uint4 per thread) ----
    {
        const uint4* src = reinterpret_cast<const uint4*>(&g_prep);
        uint4* dst = reinterpret_cast<uint4*>(&S);
#pragma unroll 4
        for (int i = tid; i < (int)PREP_U4; i += TPB) dst[i] = src[i];
    }
    __syncthreads();

    const int warp = tid >> 5, lane = tid & 31;
    const int qrow = lane >> 2;
    const int c    = (lane & 3) * 2;
    const int cp   = lane & 3;

    const uint32_t H05  = 0x38003800u;    // half2(+0.5)
    const uint32_t HN05 = 0xB800B800u;    // half2(-0.5)

    const uint32_t lm_off = (uint32_t)((lane & 7) * (WSTRIDE * 2)
                                       + ((lane >> 4) & 1) * 32
                                       + ((lane >> 3) & 1) * 16);
    const uint32_t wbase = (uint32_t)__cvta_generic_to_shared(S.W)   + lm_off;
    const uint32_t fbase = (uint32_t)__cvta_generic_to_shared(S.FCW) + lm_off;

#pragma unroll 1
    for (int it = 0; it < NTILES; it++) {
        const size_t r0 = (size_t)blockIdx.x * (128 * NTILES) + it * 128
                          + warp * 16 + qrow;

        // ---- A fragments for layer 1 from gmem (fp32 -> f16x2) ----
        uint32_t A[2][4];
#pragma unroll
        for (int q = 0; q < 2; q++) {
            const float* p0 = x + r0 * 32 + q * 16 + c;
            const float* p1 = x + (r0 + 8) * 32 + q * 16 + c;
            float2 v00 = *(const float2*)p0;
            float2 v10 = *(const float2*)p1;
            float2 v01 = *(const float2*)(p0 + 8);
            float2 v11 = *(const float2*)(p1 + 8);
            A[q][0] = pack_h2(v00.x, v00.y);
            A[q][1] = pack_h2(v10.x, v10.y);
            A[q][2] = pack_h2(v01.x, v01.y);
            A[q][3] = pack_h2(v11.x, v11.y);
        }

        // ---- 5 GRU layers ----
#pragma unroll
        for (int l = 0; l < LAYERS; l++) {
            uint32_t nA[2][4];
#pragma unroll
            for (int j = 0; j < 4; j++) {
                uint32_t Br[4], Bz[4], Bn[4];
                const uint32_t la = wbase + (uint32_t)((l * 96 + j * 8) * (WSTRIDE * 2));
                ldsm_x4(Br, la);
                ldsm_x4(Bz, la + 32 * (WSTRIDE * 2));
                ldsm_x4(Bn, la + 64 * (WSTRIDE * 2));

                const uint32_t br2 = *(const uint32_t*)&S.BG2[l * 48      + j * 4 + cp];
                const uint32_t bz2 = *(const uint32_t*)&S.BG2[l * 48 + 16 + j * 4 + cp];
                const uint32_t bi2 = *(const uint32_t*)&S.BG2[l * 48 + 32 + j * 4 + cp];
                const uint32_t bh2 = *(const uint32_t*)&S.BNH2[l * 16 + j * 4 + cp];

                uint32_t Dr2[2], Dz2[2], Dn2[2];
                mma_h_bias(Dr2, A[0], Br + 0, br2); mma_h_acc(Dr2, A[1], Br + 2);
                mma_h_bias(Dz2, A[0], Bz + 0, bz2); mma_h_acc(Dz2, A[1], Bz + 2);
                mma_h_bias(Dn2, A[0], Bn + 0, bi2); mma_h_acc(Dn2, A[1], Bn + 2);
#pragma unroll
                for (int p = 0; p < 2; p++) {
                    uint32_t rr2 = hfma2(tanh2(Dr2[p]), H05, H05);    // sigmoid
                    uint32_t zc2 = hfma2(tanh2(Dz2[p]), HN05, H05);   // 1 - z
                    uint32_t n2  = tanh2(hfma2(rr2, bh2, Dn2[p]));
                    nA[j >> 1][(j & 1) * 2 + p] = hmul2(zc2, n2);     // (1-z)*n
                }
            }
#pragma unroll
            for (int q = 0; q < 2; q++)
#pragma unroll
                for (int e = 0; e < 4; e++) A[q][e] = nA[q][e];
        }

        // ---- FC: out = H @ fc_w^T + fc_b (f32 accumulation) ----
#pragma unroll
        for (int jt = 0; jt < 4; jt++) {
            uint32_t Bf[4];
            ldsm_x4(Bf, fbase + (uint32_t)(jt * 8 * (WSTRIDE * 2)));
            const float2 fb = *(const float2*)&S.FCB[jt * 8 + c];
            float D[4];
            mma_f_bias(D, A[0], Bf + 0, fb.x, fb.y);
            mma_f_acc(D, A[1], Bf + 2);
            *(float2*)&out[r0 * 32       + jt * 8 + c] = make_float2(D[0], D[1]);
            *(float2*)&out[(r0 + 8) * 32 + jt * 8 + c] = make_float2(D[2], D[3]);
        }
    }
}

extern "C" void kernel_launch(void* const* d_in, const int* in_sizes, int n_in,
                              void* d_out, int out_size)
{
    const float* x    = (const float*)d_in[0];
    const float* w_ih = (const float*)d_in[1];
    // d_in[2] = w_hh : unused (SEQ=1, h0=0)
    const float* b_ih = (const float*)d_in[3];
    const float* b_hh = (const float*)d_in[4];
    const float* fc_w = (const float*)d_in[5];
    const float* fc_b = (const float*)d_in[6];
    float* out = (float*)d_out;

    const int batch = in_sizes[0] / 32;        // 1048576
    const int grid  = batch / (128 * NTILES);  // 2048

    gru_prep_kernel<<<40, TPB>>>(w_ih, b_ih, b_hh, fc_w, fc_b);
    gru_hmma_kernel<<<grid, TPB>>>(x, out);
}

// round 13
// speedup vs baseline: 1.1877x; 1.0365x over previous
#include <cuda_runtime.h>
#include <cuda_fp16.h>
#include <cstdint>

// GRU (SEQ=1, h0=0 => w_hh unused) via warp-level HMMA m16n8k16 fragment
// chaining. Round 13: R12 (prep kernel + vector-copy staging, NTILES=4,
// f16-accum epilogue) + R10 coalesced gmem I/O via per-warp SMEM staging:
// x: LDG.128 -> STS -> ldmatrix ; out: fragment STS -> LDS.128 -> STG.128.

#define TPB     256
#define LAYERS  5
#define WSTRIDE 40    // halves per W row (80 B): conflict-free LDSM
#define NTILES  4     // 128-row tile-halves per CTA
#define XSTR    40    // staging stride: 40 halves (x) / 40 floats (out)

struct __align__(16) Prep {
    __half  W[LAYERS * 96 * WSTRIDE];  // 38400 B  (r/z rows pre-scaled by 0.5)
    __half  FCW[32 * WSTRIDE];         //  2560 B
    __half2 BG2[LAYERS * 48];          //   960 B  r*0.5 | z*0.5 | n b_ih (pairs)
    __half2 BNH2[LAYERS * 16];         //   320 B  n-gate b_hh pairs
    float   FCB[32];                   //   128 B
};                                     // 42368 B = 2648 uint4
#define PREP_U4 (sizeof(Prep) / 16)

__device__ Prep g_prep;

// ---------------- prep kernel ----------------
__global__ void gru_prep_kernel(const float* __restrict__ w_ih,
                                const float* __restrict__ b_ih,
                                const float* __restrict__ b_hh,
                                const float* __restrict__ fc_w,
                                const float* __restrict__ fc_b)
{
    const int tid = blockIdx.x * blockDim.x + threadIdx.x;
    const int nth = gridDim.x * blockDim.x;

    for (int i = tid; i < LAYERS * 96 * 32; i += nth) {
        int l = i / 3072, row = (i % 3072) >> 5, k = i & 31;
        float scale = (row < 64) ? 0.5f : 1.0f;
        g_prep.W[(l * 96 + row) * WSTRIDE + k] = __float2half(w_ih[i] * scale);
    }
    for (int i = tid; i < 32 * 32; i += nth)
        g_prep.FCW[(i >> 5) * WSTRIDE + (i & 31)] = __float2half(fc_w[i]);
    for (int i = tid; i < LAYERS * 48; i += nth) {
        int l = i / 48, p = i % 48;
        float v0, v1;
        if (p < 16) {
            int u = l * 96 + 2 * p;
            v0 = 0.5f * (b_ih[u] + b_hh[u]);
            v1 = 0.5f * (b_ih[u + 1] + b_hh[u + 1]);
        } else if (p < 32) {
            int u = l * 96 + 32 + 2 * (p - 16);
            v0 = 0.5f * (b_ih[u] + b_hh[u]);
            v1 = 0.5f * (b_ih[u + 1] + b_hh[u + 1]);
        } else {
            int u = l * 96 + 64 + 2 * (p - 32);
            v0 = b_ih[u];
            v1 = b_ih[u + 1];
        }
        g_prep.BG2[i] = __floats2half2_rn(v0, v1);
    }
    for (int i = tid; i < LAYERS * 16; i += nth) {
        int l = i / 16, p = i % 16;
        g_prep.BNH2[i] = __floats2half2_rn(b_hh[l * 96 + 64 + 2 * p],
                                           b_hh[l * 96 + 64 + 2 * p + 1]);
    }
    for (int i = tid; i < 32; i += nth) g_prep.FCB[i] = fc_b[i];
}

// ---------------- device helpers ----------------
__device__ __forceinline__ uint32_t pack_h2(float lo, float hi) {
    uint32_t r;
    asm("cvt.rn.f16x2.f32 %0, %1, %2;" : "=r"(r) : "f"(hi), "f"(lo));
    return r;
}
__device__ __forceinline__ uint32_t tanh2(uint32_t x) {
    uint32_t y; asm("tanh.approx.f16x2 %0, %1;" : "=r"(y) : "r"(x)); return y;
}
__device__ __forceinline__ uint32_t hfma2(uint32_t a, uint32_t b, uint32_t c) {
    uint32_t d; asm("fma.rn.f16x2 %0, %1, %2, %3;" : "=r"(d) : "r"(a), "r"(b), "r"(c));
    return d;
}
__device__ __forceinline__ uint32_t hmul2(uint32_t a, uint32_t b) {
    uint32_t d; asm("mul.rn.f16x2 %0, %1, %2;" : "=r"(d) : "r"(a), "r"(b));
    return d;
}
__device__ __forceinline__ void mma_h_bias(uint32_t* d, const uint32_t* a,
                                           const uint32_t* b, uint32_t c2) {
    asm volatile(
        "mma.sync.aligned.m16n8k16.row.col.f16.f16.f16.f16 "
        "{%0,%1}, {%2,%3,%4,%5}, {%6,%7}, {%8,%8};"
        : "=r"(d[0]), "=r"(d[1])
        : "r"(a[0]), "r"(a[1]), "r"(a[2]), "r"(a[3]), "r"(b[0]), "r"(b[1]), "r"(c2));
}
__device__ __forceinline__ void mma_h_acc(uint32_t* d, const uint32_t* a,
                                          const uint32_t* b) {
    asm volatile(
        "mma.sync.aligned.m16n8k16.row.col.f16.f16.f16.f16 "
        "{%0,%1}, {%2,%3,%4,%5}, {%6,%7}, {%0,%1};"
        : "+r"(d[0]), "+r"(d[1])
        : "r"(a[0]), "r"(a[1]), "r"(a[2]), "r"(a[3]), "r"(b[0]), "r"(b[1]));
}
__device__ __forceinline__ void mma_f_bias(float* d, const uint32_t* a, const uint32_t* b,
                                           float cx, float cy) {
    asm volatile(
        "mma.sync.aligned.m16n8k16.row.col.f32.f16.f16.f32 "
        "{%0,%1,%2,%3}, {%4,%5,%6,%7}, {%8,%9}, {%10,%11,%10,%11};"
        : "=f"(d[0]), "=f"(d[1]), "=f"(d[2]), "=f"(d[3])
        : "r"(a[0]), "r"(a[1]), "r"(a[2]), "r"(a[3]), "r"(b[0]), "r"(b[1]),
          "f"(cx), "f"(cy));
}
__device__ __forceinline__ void mma_f_acc(float* d, const uint32_t* a, const uint32_t* b) {
    asm volatile(
        "mma.sync.aligned.m16n8k16.row.col.f32.f16.f16.f32 "
        "{%0,%1,%2,%3}, {%4,%5,%6,%7}, {%8,%9}, {%0,%1,%2,%3};"
        : "+f"(d[0]), "+f"(d[1]), "+f"(d[2]), "+f"(d[3])
        : "r"(a[0]), "r"(a[1]), "r"(a[2]), "r"(a[3]), "r"(b[0]), "r"(b[1]));
}
__device__ __forceinline__ void ldsm_x4(uint32_t* r, uint32_t saddr) {
    asm volatile("ldmatrix.sync.aligned.m8n8.x4.shared.b16 {%0,%1,%2,%3}, [%4];"
        : "=r"(r[0]), "=r"(r[1]), "=r"(r[2]), "=r"(r[3]) : "r"(saddr));
}

struct __align__(16) SmemAll {
    Prep  P;
    float STAGE[8][16 * XSTR];   // per-warp staging: x as fp16 / out as f32
};

__global__ void __launch_bounds__(TPB, 3)
gru_hmma_kernel(const float* __restrict__ x, float* __restrict__ out)
{
    __shared__ SmemAll S;
    const int tid = threadIdx.x;

    // ---- stage prepped package: pure vector copy ----
    {
        const uint4* src = reinterpret_cast<const uint4*>(&g_prep);
        uint4* dst = reinterpret_cast<uint4*>(&S.P);
#pragma unroll 4
        for (int i = tid; i < (int)PREP_U4; i += TPB) dst[i] = src[i];
    }
    __syncthreads();

    const int warp = tid >> 5, lane = tid & 31;
    const int qrow = lane >> 2;
    const int c    = (lane & 3) * 2;
    const int cp   = lane & 3;
    const int grp  = lane & 7;     // float4 group within a row (coalesced I/O)
    const int rr   = lane >> 3;    // base row for coalesced I/O

    const uint32_t H05  = 0x38003800u;    // half2(+0.5)
    const uint32_t HN05 = 0xB800B800u;    // half2(-0.5)

    const uint32_t lm_off = (uint32_t)((lane & 7) * (WSTRIDE * 2)
                                       + ((lane >> 4) & 1) * 32
                                       + ((lane >> 3) & 1) * 16);
    const uint32_t wbase = (uint32_t)__cvta_generic_to_shared(S.P.W)   + lm_off;
    const uint32_t fbase = (uint32_t)__cvta_generic_to_shared(S.P.FCW) + lm_off;

    float*  st  = S.STAGE[warp];
    __half* sth = reinterpret_cast<__half*>(st);
    // ldmatrix-A address into the fp16 staging (stride 80 B)
    const uint32_t abase = (uint32_t)__cvta_generic_to_shared(sth)
                           + ((lane >> 3) & 1) * (8 * XSTR * 2)
                           + (lane & 7) * (XSTR * 2)
                           + ((lane >> 4) & 1) * 16;

#pragma unroll 1
    for (int it = 0; it < NTILES; it++) {
        const size_t wrow0 = (size_t)blockIdx.x * (128 * NTILES) + it * 128 + warp * 16;
        const size_t r0 = wrow0 + qrow;

        // ---- coalesced x load -> fp16 staging ----
        {
            const float4* xg = reinterpret_cast<const float4*>(x + wrow0 * 32);
#pragma unroll
            for (int i = 0; i < 4; i++) {
                float4 v = xg[lane + 32 * i];
                uint32_t h0 = pack_h2(v.x, v.y);
                uint32_t h1 = pack_h2(v.z, v.w);
                *reinterpret_cast<uint2*>(sth + (rr + 4 * i) * XSTR + grp * 4)
                    = make_uint2(h0, h1);
            }
        }
        __syncwarp();

        // ---- A fragments via ldmatrix from staging ----
        uint32_t A[2][4];
        ldsm_x4(A[0], abase);
        ldsm_x4(A[1], abase + 32);
        __syncwarp();     // staging free for reuse (out) after this

        // ---- 5 GRU layers ----
#pragma unroll
        for (int l = 0; l < LAYERS; l++) {
            uint32_t nA[2][4];
#pragma unroll
            for (int j = 0; j < 4; j++) {
                uint32_t Br[4], Bz[4], Bn[4];
                const uint32_t la = wbase + (uint32_t)((l * 96 + j * 8) * (WSTRIDE * 2));
                ldsm_x4(Br, la);
                ldsm_x4(Bz, la + 32 * (WSTRIDE * 2));
                ldsm_x4(Bn, la + 64 * (WSTRIDE * 2));

                const uint32_t br2 = *(const uint32_t*)&S.P.BG2[l * 48      + j * 4 + cp];
                const uint32_t bz2 = *(const uint32_t*)&S.P.BG2[l * 48 + 16 + j * 4 + cp];
                const uint32_t bi2 = *(const uint32_t*)&S.P.BG2[l * 48 + 32 + j * 4 + cp];
                const uint32_t bh2 = *(const uint32_t*)&S.P.BNH2[l * 16 + j * 4 + cp];

                uint32_t Dr2[2], Dz2[2], Dn2[2];
                mma_h_bias(Dr2, A[0], Br + 0, br2); mma_h_acc(Dr2, A[1], Br + 2);
                mma_h_bias(Dz2, A[0], Bz + 0, bz2); mma_h_acc(Dz2, A[1], Bz + 2);
                mma_h_bias(Dn2, A[0], Bn + 0, bi2); mma_h_acc(Dn2, A[1], Bn + 2);
#pragma unroll
                for (int p = 0; p < 2; p++) {
                    uint32_t rr2 = hfma2(tanh2(Dr2[p]), H05, H05);    // sigmoid
                    uint32_t zc2 = hfma2(tanh2(Dz2[p]), HN05, H05);   // 1 - z
                    uint32_t n2  = tanh2(hfma2(rr2, bh2, Dn2[p]));
                    nA[j >> 1][(j & 1) * 2 + p] = hmul2(zc2, n2);     // (1-z)*n
                }
            }
#pragma unroll
            for (int q = 0; q < 2; q++)
#pragma unroll
                for (int e = 0; e < 4; e++) A[q][e] = nA[q][e];
        }

        // ---- FC -> f32 staging (fragment STS) ----
#pragma unroll
        for (int jt = 0; jt < 4; jt++) {
            uint32_t Bf[4];
            ldsm_x4(Bf, fbase + (uint32_t)(jt * 8 * (WSTRIDE * 2)));
            const float2 fb = *(const float2*)&S.P.FCB[jt * 8 + c];
            float D[4];
            mma_f_bias(D, A[0], Bf + 0, fb.x, fb.y);
            mma_f_acc(D, A[1], Bf + 2);
            *reinterpret_cast<float2*>(st + qrow * XSTR + jt * 8 + c)
                = make_float2(D[0], D[1]);
            *reinterpret_cast<float2*>(st + (qrow + 8) * XSTR + jt * 8 + c)
                = make_float2(D[2], D[3]);
        }
        __syncwarp();

        // ---- coalesced out store ----
        {
            float4* og = reinterpret_cast<float4*>(out + wrow0 * 32);
#pragma unroll
            for (int i = 0; i < 4; i++) {
                og[lane + 32 * i]
                    = *reinterpret_cast<const float4*>(st + (rr + 4 * i) * XSTR + grp * 4);
            }
        }
        __syncwarp();   // staging reused for x next iteration
    }
}

extern "C" void kernel_launch(void* const* d_in, const int* in_sizes, int n_in,
                              void* d_out, int out_size)
{
    const float* x    = (const float*)d_in[0];
    const float* w_ih = (const float*)d_in[1];
    // d_in[2] = w_hh : unused (SEQ=1, h0=0)
    const float* b_ih = (const float*)d_in[3];
    const float* b_hh = (const float*)d_in[4];
    const float* fc_w = (const float*)d_in[5];
    const float* fc_b = (const float*)d_in[6];
    float* out = (float*)d_out;

    const int batch = in_sizes[0] / 32;        // 1048576
    const int grid  = batch / (128 * NTILES);  // 2048

    gru_prep_kernel<<<40, TPB>>>(w_ih, b_ih, b_hh, fc_w, fc_b);
    gru_hmma_kernel<<<grid, TPB>>>(x, out);
}